// round 6
// baseline (speedup 1.0000x reference)
#include <cuda_runtime.h>
#include <math.h>
#include <stdint.h>

#define HH 40
#define WW 40
#define CIN 2048
#define NPIX 1600
#define CMID 256
#define NA 5
#define NBOX 8000
#define MAXDET 300

#define KSLICES 2
#define KPS (CIN / KSLICES)   // 1024
#define KC3 16
#define CHKS (KPS / KC3)      // 64 chunks
#define NPLANE (9 * KSLICES)  // 18 partial planes

// ---------------- device scratch (static, no allocation) ----------------
__device__ float g_partial[NPLANE * NPIX * CMID];
__device__ float g_x[NPIX * CMID];
__device__ float g_scores[NBOX];
__device__ float g_boxes[NBOX * 4];
__device__ float g_rois[MAXDET * 4];

__device__ __forceinline__ uint32_t smem_u32(const void* p) {
  uint32_t a;
  asm("{ .reg .u64 t; cvta.to.shared.u64 t, %1; cvt.u32.u64 %0, t; }" : "=r"(a) : "l"(p));
  return a;
}
__device__ __forceinline__ void cp16(uint32_t dst, const void* src) {
  asm volatile("cp.async.ca.shared.global [%0], [%1], 16;" ::"r"(dst), "l"(src) : "memory");
}
#define CP_COMMIT() asm volatile("cp.async.commit_group;" ::: "memory")
#define CP_WAIT0() asm volatile("cp.async.wait_group 0;" ::: "memory")

// ---------------- K1: FFMA SGEMM conv, 64x128 tile, 8x8/thread, 128 thr ----------------
// grid (25 m-tiles, 2 n-tiles, 18 tap-slices) = 900 blocks.
__global__ __launch_bounds__(128) void conv_ffma_kernel(
    const float* __restrict__ feat, const float* __restrict__ wconv) {
  __shared__ __align__(16) float As[2][KC3][64];    // 8 KB total
  __shared__ __align__(16) float Bs[2][KC3][128];   // 16 KB total

  const int mt = blockIdx.x;
  const int nt = blockIdx.y;
  const int tz = blockIdx.z;  // 0..17
  const int tap = tz >> 1;
  const int ks = tz & 1;
  const int ky = tap / 3, kx = tap % 3;
  const int tid = threadIdx.x;
  const int warp = tid >> 5;
  const int lane = tid & 31;
  const int rg = lane >> 2;            // 0..7  -> 8 m-rows
  const int cg = lane & 3;             // 0..3  -> 8 n-cols
  const int am_off = rg * 8;
  const int bn_off = warp * 32 + cg * 8;

  // A loader: m-row = tid&63, k-group = (tid>>6)*8
  const int am = tid & 63;
  const int akg = (tid >> 6) * 8;
  const int m = mt * 64 + am;
  const int y = m / WW, x = m % WW;
  const int py = y + ky - 1, px = x + kx - 1;
  const bool aval = (py >= 0 && py < HH && px >= 0 && px < WW);
  const float* arow = feat + (size_t)(aval ? (py * WW + px) : 0) * CIN + ks * KPS + akg;

  // B loader: k-row = tid>>3, n-offset = (tid&7)*16, 4x cp16
  const int bk = tid >> 3;
  const int bn = (tid & 7) * 16;
  const int n0 = nt * 128;
  const float* bsrc =
      wconv + (size_t)tap * CIN * CMID + (size_t)(ks * KPS + bk) * CMID + n0 + bn;

  float acc[8][8];
#pragma unroll
  for (int i = 0; i < 8; i++)
#pragma unroll
    for (int j = 0; j < 8; j++) acc[i][j] = 0.f;

  // prologue: chunk 0 -> buffer 0
  {
    float4 ra0 = aval ? *(const float4*)arow : make_float4(0.f, 0.f, 0.f, 0.f);
    float4 ra1 = aval ? *(const float4*)(arow + 4) : make_float4(0.f, 0.f, 0.f, 0.f);
#pragma unroll
    for (int i = 0; i < 4; i++) cp16(smem_u32(&Bs[0][bk][bn + i * 4]), bsrc + i * 4);
    CP_COMMIT();
    As[0][akg + 0][am] = ra0.x;
    As[0][akg + 1][am] = ra0.y;
    As[0][akg + 2][am] = ra0.z;
    As[0][akg + 3][am] = ra0.w;
    As[0][akg + 4][am] = ra1.x;
    As[0][akg + 5][am] = ra1.y;
    As[0][akg + 6][am] = ra1.z;
    As[0][akg + 7][am] = ra1.w;
    CP_WAIT0();
  }
  __syncthreads();

#pragma unroll 1
  for (int c = 0; c < CHKS; c++) {
    const int cur = c & 1;
    const int nxtb = cur ^ 1;
    float4 ra0, ra1;
    const bool more = (c + 1 < CHKS);
    if (more) {
      const int k0 = (c + 1) * KC3;
      ra0 = aval ? *(const float4*)(arow + k0) : make_float4(0.f, 0.f, 0.f, 0.f);
      ra1 = aval ? *(const float4*)(arow + k0 + 4) : make_float4(0.f, 0.f, 0.f, 0.f);
      const float* bs = bsrc + (size_t)k0 * CMID;
#pragma unroll
      for (int i = 0; i < 4; i++) cp16(smem_u32(&Bs[nxtb][bk][bn + i * 4]), bs + i * 4);
      CP_COMMIT();
    }
#pragma unroll
    for (int k = 0; k < KC3; k++) {
      float4 a0 = *(const float4*)&As[cur][k][am_off];
      float4 a1 = *(const float4*)&As[cur][k][am_off + 4];
      float4 b0 = *(const float4*)&Bs[cur][k][bn_off];
      float4 b1 = *(const float4*)&Bs[cur][k][bn_off + 4];
      float af[8] = {a0.x, a0.y, a0.z, a0.w, a1.x, a1.y, a1.z, a1.w};
      float bf[8] = {b0.x, b0.y, b0.z, b0.w, b1.x, b1.y, b1.z, b1.w};
#pragma unroll
      for (int i = 0; i < 8; i++)
#pragma unroll
        for (int j = 0; j < 8; j++) acc[i][j] = fmaf(af[i], bf[j], acc[i][j]);
    }
    if (more) {
      As[nxtb][akg + 0][am] = ra0.x;
      As[nxtb][akg + 1][am] = ra0.y;
      As[nxtb][akg + 2][am] = ra0.z;
      As[nxtb][akg + 3][am] = ra0.w;
      As[nxtb][akg + 4][am] = ra1.x;
      As[nxtb][akg + 5][am] = ra1.y;
      As[nxtb][akg + 6][am] = ra1.z;
      As[nxtb][akg + 7][am] = ra1.w;
      CP_WAIT0();
    }
    __syncthreads();
  }

  // epilogue: write 8 rows x 8 cols per thread
  float* base = g_partial + (size_t)tz * (NPIX * CMID);
#pragma unroll
  for (int i = 0; i < 8; i++) {
    const int mr = mt * 64 + am_off + i;
    float* dst = &base[(size_t)mr * CMID + n0 + bn_off];
    *(float4*)dst = make_float4(acc[i][0], acc[i][1], acc[i][2], acc[i][3]);
    *(float4*)(dst + 4) = make_float4(acc[i][4], acc[i][5], acc[i][6], acc[i][7]);
  }
}

// ---------------- K2: reduce 18 partials + bias + relu ----------------
__global__ __launch_bounds__(256) void reduce_bias_relu(const float* __restrict__ bias) {
  int i = blockIdx.x * 256 + threadIdx.x;
  float s = bias[i & 255];
#pragma unroll
  for (int t = 0; t < NPLANE; t++) s += g_partial[(size_t)t * (NPIX * CMID) + i];
  g_x[i] = fmaxf(s, 0.f);
}

// ---------------- K3: 1x1 heads + score + anchor decode ----------------
__global__ __launch_bounds__(32) void head_conv_kernel(
    const float* __restrict__ cls_w, const float* __restrict__ cls_b,
    const float* __restrict__ reg_w, const float* __restrict__ reg_b) {
  const int p = blockIdx.x;
  const int lane = threadIdx.x;
  const float* xr = g_x + (size_t)p * CMID;
  float acc[30];
#pragma unroll
  for (int o = 0; o < 30; o++) acc[o] = 0.f;
  for (int k = lane; k < CMID; k += 32) {
    float xv = xr[k];
    const float* wc = cls_w + (size_t)k * 10;
#pragma unroll
    for (int o = 0; o < 10; o++) acc[o] = fmaf(xv, wc[o], acc[o]);
    const float* wr = reg_w + (size_t)k * 20;
#pragma unroll
    for (int o = 0; o < 20; o++) acc[10 + o] = fmaf(xv, wr[o], acc[10 + o]);
  }
#pragma unroll
  for (int o = 0; o < 30; o++) {
#pragma unroll
    for (int s = 16; s > 0; s >>= 1) acc[o] += __shfl_xor_sync(0xffffffffu, acc[o], s);
  }
  if (lane < NA) {
    const int a = lane;
    float l0 = acc[2 * a + 0] + cls_b[2 * a + 0];
    float l1 = acc[2 * a + 1] + cls_b[2 * a + 1];
    float score = 1.f / (1.f + expf(l0 - l1));
    float d0 = acc[10 + 4 * a + 0] + reg_b[4 * a + 0];
    float d1 = acc[10 + 4 * a + 1] + reg_b[4 * a + 1];
    float d2 = acc[10 + 4 * a + 2] + reg_b[4 * a + 2];
    float d3 = acc[10 + 4 * a + 3] + reg_b[4 * a + 3];
    float base = 32.f * (float)(1 << a);
    float wdt = expf(d2) * base;
    float hgt = expf(d3) * base;
    float xc = (float)(p % WW) + d0;
    float yc = (float)(p / WW) + d1;
    const int n = p * NA + a;
    g_scores[n] = score;
    float4 b = make_float4(xc - 0.5f * wdt, yc - 0.5f * hgt,
                           xc + 0.5f * wdt, yc + 0.5f * hgt);
    *(float4*)&g_boxes[n * 4] = b;
  }
}

// ---------------- K4: fused argmax-greedy NMS (no sort) ----------------
// Round: block argmax over unsuppressed (score desc, idx asc) -> keep ->
// suppress all IoU >= 0.7 (incl. itself). Equivalent to sorted greedy NMS.
__global__ __launch_bounds__(1024) void nms_fused_kernel() {
  extern __shared__ float sb[];  // 6 * 8000 floats = 192 KB
  float* bx1 = sb;
  float* by1 = sb + NBOX;
  float* bx2 = sb + 2 * NBOX;
  float* by2 = sb + 3 * NBOX;
  float* bar = sb + 4 * NBOX;
  float* bsc = sb + 5 * NBOX;
  __shared__ float wbest[32];
  __shared__ int widx[32];
  __shared__ int s_bi;
  const int t = threadIdx.x;
  const int lane = t & 31;
  const int warp = t >> 5;

  for (int i = t; i < NBOX; i += 1024) {
    float4 b = *(const float4*)&g_boxes[i * 4];
    bx1[i] = b.x; by1[i] = b.y; bx2[i] = b.z; by2[i] = b.w;
    bar[i] = (b.z - b.x) * (b.w - b.y);
    bsc[i] = g_scores[i];
  }
  __syncthreads();

  int count = 0;
  for (;;) {
    // --- block argmax (score desc, idx asc) ---
    float bs = -1.f;
    int bi = -1;
    for (int i = t; i < NBOX; i += 1024) {
      float s = bsc[i];
      if (s > bs) { bs = s; bi = i; }  // within-thread i increases: keeps smallest idx on tie
    }
#pragma unroll
    for (int s = 16; s > 0; s >>= 1) {
      float os = __shfl_xor_sync(0xffffffffu, bs, s);
      int oi = __shfl_xor_sync(0xffffffffu, bi, s);
      if (os > bs || (os == bs && oi >= 0 && (bi < 0 || oi < bi))) { bs = os; bi = oi; }
    }
    if (lane == 0) { wbest[warp] = bs; widx[warp] = bi; }
    __syncthreads();
    if (warp == 0) {
      bs = wbest[lane];
      bi = widx[lane];
#pragma unroll
      for (int s = 16; s > 0; s >>= 1) {
        float os = __shfl_xor_sync(0xffffffffu, bs, s);
        int oi = __shfl_xor_sync(0xffffffffu, bi, s);
        if (os > bs || (os == bs && oi >= 0 && (bi < 0 || oi < bi))) { bs = os; bi = oi; }
      }
      if (lane == 0) s_bi = (bs < 0.f) ? -1 : bi;
    }
    __syncthreads();
    const int i = s_bi;
    if (i < 0) break;
    if (t == 0) {
      *(float4*)&g_rois[count * 4] = make_float4(bx1[i], by1[i], bx2[i], by2[i]);
    }
    count++;
    // --- suppress everything with IoU >= 0.7 vs box i (removes i too) ---
    const float ix1 = bx1[i], iy1 = by1[i], ix2 = bx2[i], iy2 = by2[i], ia = bar[i];
    for (int j = t; j < NBOX; j += 1024) {
      if (bsc[j] >= 0.f) {
        float iw = fmaxf(fminf(ix2, bx2[j]) - fmaxf(ix1, bx1[j]), 0.f);
        float ih = fmaxf(fminf(iy2, by2[j]) - fmaxf(iy1, by1[j]), 0.f);
        float inter = iw * ih;
        float iou = inter / (ia + bar[j] - inter);
        if (iou >= 0.7f) bsc[j] = -1.f;
      }
    }
    if (count >= MAXDET) break;
    __syncthreads();
  }
  __syncthreads();
  for (int r = count + t; r < MAXDET; r += 1024) {
    *(float4*)&g_rois[r * 4] = make_float4(0.f, 0.f, 0.f, 0.f);
  }
}

// ---------------- K6: FC head on 300 ROIs + final outputs ----------------
__global__ __launch_bounds__(128) void fc_head_kernel(
    const float* __restrict__ fc1_w, const float* __restrict__ fc1_b,
    const float* __restrict__ clsh_w, const float* __restrict__ clsh_b,
    const float* __restrict__ regh_w, const float* __restrict__ regh_b,
    float* __restrict__ out) {
  const int r = blockIdx.x;
  const int t = threadIdx.x;
  float4 roi = *(const float4*)&g_rois[r * 4];
  float part[8];
#pragma unroll
  for (int o = 0; o < 8; o++) part[o] = 0.f;
  for (int j = t; j < 1024; j += 128) {
    float f = fc1_b[j] + roi.x * fc1_w[j] + roi.y * fc1_w[1024 + j] +
              roi.z * fc1_w[2048 + j] + roi.w * fc1_w[3072 + j];
    f = fmaxf(f, 0.f);
    float4 cw = *(const float4*)&clsh_w[j * 4];
    float4 rw = *(const float4*)&regh_w[j * 4];
    part[0] += f * cw.x; part[1] += f * cw.y; part[2] += f * cw.z; part[3] += f * cw.w;
    part[4] += f * rw.x; part[5] += f * rw.y; part[6] += f * rw.z; part[7] += f * rw.w;
  }
#pragma unroll
  for (int o = 0; o < 8; o++) {
#pragma unroll
    for (int s = 16; s > 0; s >>= 1) part[o] += __shfl_xor_sync(0xffffffffu, part[o], s);
  }
  __shared__ float wred[4][8];
  const int warp = t >> 5, lane = t & 31;
  if (lane == 0) {
#pragma unroll
    for (int o = 0; o < 8; o++) wred[warp][o] = part[o];
  }
  __syncthreads();
  if (t == 0) {
    float v[8];
#pragma unroll
    for (int o = 0; o < 8; o++) v[o] = wred[0][o] + wred[1][o] + wred[2][o] + wred[3][o];
    float l0 = v[0] + clsh_b[0], l1 = v[1] + clsh_b[1];
    float l2 = v[2] + clsh_b[2], l3 = v[3] + clsh_b[3];
    float mx = fmaxf(fmaxf(l0, l1), fmaxf(l2, l3));
    float e0 = expf(l0 - mx), e1 = expf(l1 - mx), e2 = expf(l2 - mx), e3 = expf(l3 - mx);
    float inv = 1.f / (e0 + e1 + e2 + e3);
    out[r * 4 + 0] = e0 * inv;
    out[r * 4 + 1] = e1 * inv;
    out[r * 4 + 2] = e2 * inv;
    out[r * 4 + 3] = e3 * inv;
    out[1200 + r * 4 + 0] = v[4] + regh_b[0];
    out[1200 + r * 4 + 1] = v[5] + regh_b[1];
    out[1200 + r * 4 + 2] = v[6] + regh_b[2];
    out[1200 + r * 4 + 3] = v[7] + regh_b[3];
    *(float4*)&out[2400 + r * 4] = roi;
  }
}

// ---------------- launch ----------------
extern "C" void kernel_launch(void* const* d_in, const int* in_sizes, int n_in,
                              void* d_out, int out_size) {
  const float* feat   = (const float*)d_in[0];
  const float* conv_w = (const float*)d_in[1];
  const float* conv_b = (const float*)d_in[2];
  const float* cls_w  = (const float*)d_in[3];
  const float* cls_b  = (const float*)d_in[4];
  const float* reg_w  = (const float*)d_in[5];
  const float* reg_b  = (const float*)d_in[6];
  const float* fc1_w  = (const float*)d_in[7];
  const float* fc1_b  = (const float*)d_in[8];
  const float* clsh_w = (const float*)d_in[9];
  const float* clsh_b = (const float*)d_in[10];
  const float* regh_w = (const float*)d_in[11];
  const float* regh_b = (const float*)d_in[12];
  float* out = (float*)d_out;

  (void)in_sizes; (void)n_in; (void)out_size;

  cudaFuncSetAttribute(nms_fused_kernel, cudaFuncAttributeMaxDynamicSharedMemorySize,
                       NBOX * 6 * 4);

  conv_ffma_kernel<<<dim3(25, 2, NPLANE), 128>>>(feat, conv_w);
  reduce_bias_relu<<<1600, 256>>>(conv_b);
  head_conv_kernel<<<1600, 32>>>(cls_w, cls_b, reg_w, reg_b);
  nms_fused_kernel<<<1, 1024, NBOX * 6 * 4>>>();
  fc_head_kernel<<<300, 128>>>(fc1_w, fc1_b, clsh_w, clsh_b, regh_w, regh_b, out);
}

// round 7
// speedup vs baseline: 1.0088x; 1.0088x over previous
#include <cuda_runtime.h>
#include <math.h>
#include <stdint.h>

#define HH 40
#define WW 40
#define CIN 2048
#define NPIX 1600
#define CMID 256
#define NA 5
#define NBOX 8000
#define NWORD 125
#define MAXDET 300

#define KSLICES 2
#define KPS (CIN / KSLICES)   // 1024
#define KC3 16
#define CHKS (KPS / KC3)      // 64 chunks
#define NPLANE (9 * KSLICES)  // 18 partial planes

// ---------------- device scratch (static, no allocation) ----------------
__device__ float g_partial[NPLANE * NPIX * CMID];
__device__ float g_x[NPIX * CMID];
__device__ float g_scores[NBOX];
__device__ float g_boxes[NBOX * 4];
__device__ float g_boxsorted[NBOX * 4];
__device__ float g_rois[MAXDET * 4];

__device__ __forceinline__ uint32_t smem_u32(const void* p) {
  uint32_t a;
  asm("{ .reg .u64 t; cvta.to.shared.u64 t, %1; cvt.u32.u64 %0, t; }" : "=r"(a) : "l"(p));
  return a;
}
__device__ __forceinline__ void cp16(uint32_t dst, const void* src) {
  asm volatile("cp.async.ca.shared.global [%0], [%1], 16;" ::"r"(dst), "l"(src) : "memory");
}
#define CP_COMMIT() asm volatile("cp.async.commit_group;" ::: "memory")
#define CP_WAIT0() asm volatile("cp.async.wait_group 0;" ::: "memory")

// ---------------- K1: FFMA SGEMM conv, 64x128 tile, 8x8/thread, 128 thr ----------------
__global__ __launch_bounds__(128) void conv_ffma_kernel(
    const float* __restrict__ feat, const float* __restrict__ wconv) {
  __shared__ __align__(16) float As[2][KC3][64];
  __shared__ __align__(16) float Bs[2][KC3][128];

  const int mt = blockIdx.x;
  const int nt = blockIdx.y;
  const int tz = blockIdx.z;  // 0..17
  const int tap = tz >> 1;
  const int ks = tz & 1;
  const int ky = tap / 3, kx = tap % 3;
  const int tid = threadIdx.x;
  const int warp = tid >> 5;
  const int lane = tid & 31;
  const int rg = lane >> 2;
  const int cg = lane & 3;
  const int am_off = rg * 8;
  const int bn_off = warp * 32 + cg * 8;

  const int am = tid & 63;
  const int akg = (tid >> 6) * 8;
  const int m = mt * 64 + am;
  const int y = m / WW, x = m % WW;
  const int py = y + ky - 1, px = x + kx - 1;
  const bool aval = (py >= 0 && py < HH && px >= 0 && px < WW);
  const float* arow = feat + (size_t)(aval ? (py * WW + px) : 0) * CIN + ks * KPS + akg;

  const int bk = tid >> 3;
  const int bn = (tid & 7) * 16;
  const int n0 = nt * 128;
  const float* bsrc =
      wconv + (size_t)tap * CIN * CMID + (size_t)(ks * KPS + bk) * CMID + n0 + bn;

  float acc[8][8];
#pragma unroll
  for (int i = 0; i < 8; i++)
#pragma unroll
    for (int j = 0; j < 8; j++) acc[i][j] = 0.f;

  {
    float4 ra0 = aval ? *(const float4*)arow : make_float4(0.f, 0.f, 0.f, 0.f);
    float4 ra1 = aval ? *(const float4*)(arow + 4) : make_float4(0.f, 0.f, 0.f, 0.f);
#pragma unroll
    for (int i = 0; i < 4; i++) cp16(smem_u32(&Bs[0][bk][bn + i * 4]), bsrc + i * 4);
    CP_COMMIT();
    As[0][akg + 0][am] = ra0.x;
    As[0][akg + 1][am] = ra0.y;
    As[0][akg + 2][am] = ra0.z;
    As[0][akg + 3][am] = ra0.w;
    As[0][akg + 4][am] = ra1.x;
    As[0][akg + 5][am] = ra1.y;
    As[0][akg + 6][am] = ra1.z;
    As[0][akg + 7][am] = ra1.w;
    CP_WAIT0();
  }
  __syncthreads();

#pragma unroll 1
  for (int c = 0; c < CHKS; c++) {
    const int cur = c & 1;
    const int nxtb = cur ^ 1;
    float4 ra0, ra1;
    const bool more = (c + 1 < CHKS);
    if (more) {
      const int k0 = (c + 1) * KC3;
      ra0 = aval ? *(const float4*)(arow + k0) : make_float4(0.f, 0.f, 0.f, 0.f);
      ra1 = aval ? *(const float4*)(arow + k0 + 4) : make_float4(0.f, 0.f, 0.f, 0.f);
      const float* bs = bsrc + (size_t)k0 * CMID;
#pragma unroll
      for (int i = 0; i < 4; i++) cp16(smem_u32(&Bs[nxtb][bk][bn + i * 4]), bs + i * 4);
      CP_COMMIT();
    }
#pragma unroll
    for (int k = 0; k < KC3; k++) {
      float4 a0 = *(const float4*)&As[cur][k][am_off];
      float4 a1 = *(const float4*)&As[cur][k][am_off + 4];
      float4 b0 = *(const float4*)&Bs[cur][k][bn_off];
      float4 b1 = *(const float4*)&Bs[cur][k][bn_off + 4];
      float af[8] = {a0.x, a0.y, a0.z, a0.w, a1.x, a1.y, a1.z, a1.w};
      float bf[8] = {b0.x, b0.y, b0.z, b0.w, b1.x, b1.y, b1.z, b1.w};
#pragma unroll
      for (int i = 0; i < 8; i++)
#pragma unroll
        for (int j = 0; j < 8; j++) acc[i][j] = fmaf(af[i], bf[j], acc[i][j]);
    }
    if (more) {
      As[nxtb][akg + 0][am] = ra0.x;
      As[nxtb][akg + 1][am] = ra0.y;
      As[nxtb][akg + 2][am] = ra0.z;
      As[nxtb][akg + 3][am] = ra0.w;
      As[nxtb][akg + 4][am] = ra1.x;
      As[nxtb][akg + 5][am] = ra1.y;
      As[nxtb][akg + 6][am] = ra1.z;
      As[nxtb][akg + 7][am] = ra1.w;
      CP_WAIT0();
    }
    __syncthreads();
  }

  float* base = g_partial + (size_t)tz * (NPIX * CMID);
#pragma unroll
  for (int i = 0; i < 8; i++) {
    const int mr = mt * 64 + am_off + i;
    float* dst = &base[(size_t)mr * CMID + n0 + bn_off];
    *(float4*)dst = make_float4(acc[i][0], acc[i][1], acc[i][2], acc[i][3]);
    *(float4*)(dst + 4) = make_float4(acc[i][4], acc[i][5], acc[i][6], acc[i][7]);
  }
}

// ---------------- K2: reduce 18 partials + bias + relu ----------------
__global__ __launch_bounds__(256) void reduce_bias_relu(const float* __restrict__ bias) {
  int i = blockIdx.x * 256 + threadIdx.x;
  float s = bias[i & 255];
#pragma unroll
  for (int t = 0; t < NPLANE; t++) s += g_partial[(size_t)t * (NPIX * CMID) + i];
  g_x[i] = fmaxf(s, 0.f);
}

// ---------------- K3: 1x1 heads + score + anchor decode ----------------
__global__ __launch_bounds__(32) void head_conv_kernel(
    const float* __restrict__ cls_w, const float* __restrict__ cls_b,
    const float* __restrict__ reg_w, const float* __restrict__ reg_b) {
  const int p = blockIdx.x;
  const int lane = threadIdx.x;
  const float* xr = g_x + (size_t)p * CMID;
  float acc[30];
#pragma unroll
  for (int o = 0; o < 30; o++) acc[o] = 0.f;
  for (int k = lane; k < CMID; k += 32) {
    float xv = xr[k];
    const float* wc = cls_w + (size_t)k * 10;
#pragma unroll
    for (int o = 0; o < 10; o++) acc[o] = fmaf(xv, wc[o], acc[o]);
    const float* wr = reg_w + (size_t)k * 20;
#pragma unroll
    for (int o = 0; o < 20; o++) acc[10 + o] = fmaf(xv, wr[o], acc[10 + o]);
  }
#pragma unroll
  for (int o = 0; o < 30; o++) {
#pragma unroll
    for (int s = 16; s > 0; s >>= 1) acc[o] += __shfl_xor_sync(0xffffffffu, acc[o], s);
  }
  if (lane < NA) {
    const int a = lane;
    float l0 = acc[2 * a + 0] + cls_b[2 * a + 0];
    float l1 = acc[2 * a + 1] + cls_b[2 * a + 1];
    float score = 1.f / (1.f + expf(l0 - l1));
    float d0 = acc[10 + 4 * a + 0] + reg_b[4 * a + 0];
    float d1 = acc[10 + 4 * a + 1] + reg_b[4 * a + 1];
    float d2 = acc[10 + 4 * a + 2] + reg_b[4 * a + 2];
    float d3 = acc[10 + 4 * a + 3] + reg_b[4 * a + 3];
    float base = 32.f * (float)(1 << a);
    float wdt = expf(d2) * base;
    float hgt = expf(d3) * base;
    float xc = (float)(p % WW) + d0;
    float yc = (float)(p / WW) + d1;
    const int n = p * NA + a;
    g_scores[n] = score;
    float4 b = make_float4(xc - 0.5f * wdt, yc - 0.5f * hgt,
                           xc + 0.5f * wdt, yc + 0.5f * hgt);
    *(float4*)&g_boxes[n * 4] = b;
  }
}

// ---------------- K4: single-block LSD radix sort (32 x 1-bit stable splits) ----------------
// key = ~ordered(score): ascending key == (score desc); stability gives idx asc on ties.
__global__ __launch_bounds__(1024) void radix_sort_kernel() {
  extern __shared__ uint32_t s[];  // 4 * 8192 * 4B = 128 KB
  uint32_t* keyb[2] = {s, s + 16384};
  uint32_t* idxb[2] = {s + 8192, s + 24576};
  __shared__ uint32_t warptot[32], warpoff[32];
  __shared__ uint32_t s_totzero;
  const int t = threadIdx.x;
  const int lane = t & 31, warp = t >> 5;

  for (int i = t; i < 8192; i += 1024) {
    uint32_t kv;
    if (i < NBOX) {
      uint32_t u = __float_as_uint(g_scores[i]);
      uint32_t ou = (u & 0x80000000u) ? ~u : (u | 0x80000000u);
      kv = ~ou;
    } else {
      kv = 0xFFFFFFFFu;
    }
    keyb[0][i] = kv;
    idxb[0][i] = (uint32_t)i;
  }
  __syncthreads();

  int cur = 0;
  const int base = t * 8;
#pragma unroll 1
  for (int b = 0; b < 32; b++) {
    uint32_t k[8], v[8];
#pragma unroll
    for (int e = 0; e < 8; e++) {
      k[e] = keyb[cur][base + e];
      v[e] = idxb[cur][base + e];
    }
    int zeros = 0;
#pragma unroll
    for (int e = 0; e < 8; e++) zeros += (int)(((k[e] >> b) & 1u) ^ 1u);
    // warp inclusive scan of zeros
    int ex = zeros;
#pragma unroll
    for (int s2 = 1; s2 < 32; s2 <<= 1) {
      int o = __shfl_up_sync(0xffffffffu, ex, s2);
      if (lane >= s2) ex += o;
    }
    const int incl = ex;
    ex -= zeros;  // exclusive within warp
    if (lane == 31) warptot[warp] = (uint32_t)incl;
    __syncthreads();
    if (warp == 0) {
      int wv = (int)warptot[lane];
      int wex = wv;
#pragma unroll
      for (int s2 = 1; s2 < 32; s2 <<= 1) {
        int o = __shfl_up_sync(0xffffffffu, wex, s2);
        if (lane >= s2) wex += o;
      }
      warpoff[lane] = (uint32_t)(wex - wv);
      if (lane == 31) s_totzero = (uint32_t)wex;
    }
    __syncthreads();
    const int zp = (int)warpoff[warp] + ex;  // zeros before this thread
    const int op = base - zp;                // ones before this thread
    const int tz = (int)s_totzero;
    const int nxt = cur ^ 1;
    int zc = 0, oc = 0;
#pragma unroll
    for (int e = 0; e < 8; e++) {
      const int bit = (int)((k[e] >> b) & 1u);
      const int pos = bit ? (tz + op + oc++) : (zp + zc++);
      keyb[nxt][pos] = k[e];
      idxb[nxt][pos] = v[e];
    }
    cur = nxt;
    __syncthreads();
  }

  for (int i = t; i < NBOX; i += 1024) {
    uint32_t id = idxb[cur][i];
    *(float4*)&g_boxsorted[i * 4] = *(const float4*)&g_boxes[id * 4];
  }
}

// ---------------- K5: greedy NMS (bitmask find-next, suppress j>i) ----------------
__global__ __launch_bounds__(1024) void nms_kernel() {
  extern __shared__ float sb[];  // 5 * 8000 floats
  float* bx1 = sb;
  float* by1 = sb + NBOX;
  float* bx2 = sb + 2 * NBOX;
  float* by2 = sb + 3 * NBOX;
  float* bar = sb + 4 * NBOX;
  __shared__ unsigned long long remv[NWORD];
  __shared__ int ssel[MAXDET];
  __shared__ int s_next;
  const int t = threadIdx.x;
  for (int i = t; i < NBOX; i += 1024) {
    float4 b = *(const float4*)&g_boxsorted[i * 4];
    bx1[i] = b.x; by1[i] = b.y; bx2[i] = b.z; by2[i] = b.w;
    bar[i] = (b.z - b.x) * (b.w - b.y);
  }
  if (t < NWORD) remv[t] = 0ull;
  __syncthreads();

  int count = 0, cur = 0;
  for (;;) {
    if (t == 0) s_next = 0x7FFFFFFF;
    __syncthreads();
    const int wstart = cur >> 6;
    if (t >= wstart && t < NWORD) {
      unsigned long long mw = ~remv[t];
      if (t == wstart) mw &= (~0ull) << (cur & 63);
      if (mw) atomicMin(&s_next, (t << 6) + (__ffsll((long long)mw) - 1));
    }
    __syncthreads();
    const int i = s_next;
    if (i == 0x7FFFFFFF) break;
    if (t == 0) ssel[count] = i;
    count++;
    const float ix1 = bx1[i], iy1 = by1[i], ix2 = bx2[i], iy2 = by2[i], ia = bar[i];
    for (int j = i + 1 + t; j < NBOX; j += 1024) {
      float iw = fminf(ix2, bx2[j]) - fmaxf(ix1, bx1[j]);
      float ih = fminf(iy2, by2[j]) - fmaxf(iy1, by1[j]);
      iw = fmaxf(iw, 0.f);
      ih = fmaxf(ih, 0.f);
      float inter = iw * ih;
      float iou = inter / (ia + bar[j] - inter);
      if (iou >= 0.7f) atomicOr(&remv[j >> 6], 1ull << (j & 63));
    }
    cur = i + 1;
    if (count >= MAXDET) break;
    __syncthreads();
  }
  __syncthreads();
  for (int r = t; r < MAXDET; r += 1024) {
    float4 v = make_float4(0.f, 0.f, 0.f, 0.f);
    if (r < count) {
      int i = ssel[r];
      v = make_float4(bx1[i], by1[i], bx2[i], by2[i]);
    }
    *(float4*)&g_rois[r * 4] = v;
  }
}

// ---------------- K6: FC head on 300 ROIs + final outputs ----------------
__global__ __launch_bounds__(128) void fc_head_kernel(
    const float* __restrict__ fc1_w, const float* __restrict__ fc1_b,
    const float* __restrict__ clsh_w, const float* __restrict__ clsh_b,
    const float* __restrict__ regh_w, const float* __restrict__ regh_b,
    float* __restrict__ out) {
  const int r = blockIdx.x;
  const int t = threadIdx.x;
  float4 roi = *(const float4*)&g_rois[r * 4];
  float part[8];
#pragma unroll
  for (int o = 0; o < 8; o++) part[o] = 0.f;
  for (int j = t; j < 1024; j += 128) {
    float f = fc1_b[j] + roi.x * fc1_w[j] + roi.y * fc1_w[1024 + j] +
              roi.z * fc1_w[2048 + j] + roi.w * fc1_w[3072 + j];
    f = fmaxf(f, 0.f);
    float4 cw = *(const float4*)&clsh_w[j * 4];
    float4 rw = *(const float4*)&regh_w[j * 4];
    part[0] += f * cw.x; part[1] += f * cw.y; part[2] += f * cw.z; part[3] += f * cw.w;
    part[4] += f * rw.x; part[5] += f * rw.y; part[6] += f * rw.z; part[7] += f * rw.w;
  }
#pragma unroll
  for (int o = 0; o < 8; o++) {
#pragma unroll
    for (int s = 16; s > 0; s >>= 1) part[o] += __shfl_xor_sync(0xffffffffu, part[o], s);
  }
  __shared__ float wred[4][8];
  const int warp = t >> 5, lane = t & 31;
  if (lane == 0) {
#pragma unroll
    for (int o = 0; o < 8; o++) wred[warp][o] = part[o];
  }
  __syncthreads();
  if (t == 0) {
    float v[8];
#pragma unroll
    for (int o = 0; o < 8; o++) v[o] = wred[0][o] + wred[1][o] + wred[2][o] + wred[3][o];
    float l0 = v[0] + clsh_b[0], l1 = v[1] + clsh_b[1];
    float l2 = v[2] + clsh_b[2], l3 = v[3] + clsh_b[3];
    float mx = fmaxf(fmaxf(l0, l1), fmaxf(l2, l3));
    float e0 = expf(l0 - mx), e1 = expf(l1 - mx), e2 = expf(l2 - mx), e3 = expf(l3 - mx);
    float inv = 1.f / (e0 + e1 + e2 + e3);
    out[r * 4 + 0] = e0 * inv;
    out[r * 4 + 1] = e1 * inv;
    out[r * 4 + 2] = e2 * inv;
    out[r * 4 + 3] = e3 * inv;
    out[1200 + r * 4 + 0] = v[4] + regh_b[0];
    out[1200 + r * 4 + 1] = v[5] + regh_b[1];
    out[1200 + r * 4 + 2] = v[6] + regh_b[2];
    out[1200 + r * 4 + 3] = v[7] + regh_b[3];
    *(float4*)&out[2400 + r * 4] = roi;
  }
}

// ---------------- launch ----------------
extern "C" void kernel_launch(void* const* d_in, const int* in_sizes, int n_in,
                              void* d_out, int out_size) {
  const float* feat   = (const float*)d_in[0];
  const float* conv_w = (const float*)d_in[1];
  const float* conv_b = (const float*)d_in[2];
  const float* cls_w  = (const float*)d_in[3];
  const float* cls_b  = (const float*)d_in[4];
  const float* reg_w  = (const float*)d_in[5];
  const float* reg_b  = (const float*)d_in[6];
  const float* fc1_w  = (const float*)d_in[7];
  const float* fc1_b  = (const float*)d_in[8];
  const float* clsh_w = (const float*)d_in[9];
  const float* clsh_b = (const float*)d_in[10];
  const float* regh_w = (const float*)d_in[11];
  const float* regh_b = (const float*)d_in[12];
  float* out = (float*)d_out;

  (void)in_sizes; (void)n_in; (void)out_size;

  cudaFuncSetAttribute(radix_sort_kernel, cudaFuncAttributeMaxDynamicSharedMemorySize,
                       4 * 8192 * 4);
  cudaFuncSetAttribute(nms_kernel, cudaFuncAttributeMaxDynamicSharedMemorySize, NBOX * 5 * 4);

  conv_ffma_kernel<<<dim3(25, 2, NPLANE), 128>>>(feat, conv_w);
  reduce_bias_relu<<<1600, 256>>>(conv_b);
  head_conv_kernel<<<1600, 32>>>(cls_w, cls_b, reg_w, reg_b);
  radix_sort_kernel<<<1, 1024, 4 * 8192 * 4>>>();
  nms_kernel<<<1, 1024, NBOX * 5 * 4>>>();
  fc_head_kernel<<<300, 128>>>(fc1_w, fc1_b, clsh_w, clsh_b, regh_w, regh_b, out);
}

// round 8
// speedup vs baseline: 1.6952x; 1.6805x over previous
#include <cuda_runtime.h>
#include <math.h>
#include <stdint.h>

#define HH 40
#define WW 40
#define CIN 2048
#define NPIX 1600
#define CMID 256
#define NA 5
#define NBOX 8000
#define NWORD 125
#define MAXDET 300

#define KSLICES 2
#define KPS (CIN / KSLICES)   // 1024
#define KC3 16
#define CHKS (KPS / KC3)      // 64 chunks
#define NPLANE (9 * KSLICES)  // 18 partial planes

// ---------------- device scratch (static, no allocation) ----------------
__device__ float g_partial[NPLANE * NPIX * CMID];
__device__ float g_x[NPIX * CMID];
__device__ float g_scores[NBOX];
__device__ float g_boxes[NBOX * 4];
__device__ float g_boxsorted[NBOX * 4];
__device__ int g_rank[NBOX];
__device__ unsigned long long g_mask[(size_t)NBOX * NWORD];  // 8 MB
__device__ float g_rois[MAXDET * 4];

__device__ __forceinline__ uint32_t smem_u32(const void* p) {
  uint32_t a;
  asm("{ .reg .u64 t; cvta.to.shared.u64 t, %1; cvt.u32.u64 %0, t; }" : "=r"(a) : "l"(p));
  return a;
}
__device__ __forceinline__ void cp16(uint32_t dst, const void* src) {
  asm volatile("cp.async.ca.shared.global [%0], [%1], 16;" ::"r"(dst), "l"(src) : "memory");
}
#define CP_COMMIT() asm volatile("cp.async.commit_group;" ::: "memory")
#define CP_WAIT0() asm volatile("cp.async.wait_group 0;" ::: "memory")

__device__ __forceinline__ unsigned long long score_key(int i) {
  uint32_t u = __float_as_uint(g_scores[i]);
  uint32_t ou = (u & 0x80000000u) ? ~u : (u | 0x80000000u);
  return ((unsigned long long)(~ou) << 13) | (unsigned)i;  // asc key == score desc, idx asc
}

// ---------------- K1: FFMA SGEMM conv, 64x128 tile, 8x8/thread, 128 thr ----------------
__global__ __launch_bounds__(128) void conv_ffma_kernel(
    const float* __restrict__ feat, const float* __restrict__ wconv) {
  __shared__ __align__(16) float As[2][KC3][64];
  __shared__ __align__(16) float Bs[2][KC3][128];

  const int mt = blockIdx.x;
  const int nt = blockIdx.y;
  const int tz = blockIdx.z;
  const int tap = tz >> 1;
  const int ks = tz & 1;
  const int ky = tap / 3, kx = tap % 3;
  const int tid = threadIdx.x;
  const int warp = tid >> 5;
  const int lane = tid & 31;
  const int rg = lane >> 2;
  const int cg = lane & 3;
  const int am_off = rg * 8;
  const int bn_off = warp * 32 + cg * 8;

  const int am = tid & 63;
  const int akg = (tid >> 6) * 8;
  const int m = mt * 64 + am;
  const int y = m / WW, x = m % WW;
  const int py = y + ky - 1, px = x + kx - 1;
  const bool aval = (py >= 0 && py < HH && px >= 0 && px < WW);
  const float* arow = feat + (size_t)(aval ? (py * WW + px) : 0) * CIN + ks * KPS + akg;

  const int bk = tid >> 3;
  const int bn = (tid & 7) * 16;
  const int n0 = nt * 128;
  const float* bsrc =
      wconv + (size_t)tap * CIN * CMID + (size_t)(ks * KPS + bk) * CMID + n0 + bn;

  float acc[8][8];
#pragma unroll
  for (int i = 0; i < 8; i++)
#pragma unroll
    for (int j = 0; j < 8; j++) acc[i][j] = 0.f;

  {
    float4 ra0 = aval ? *(const float4*)arow : make_float4(0.f, 0.f, 0.f, 0.f);
    float4 ra1 = aval ? *(const float4*)(arow + 4) : make_float4(0.f, 0.f, 0.f, 0.f);
#pragma unroll
    for (int i = 0; i < 4; i++) cp16(smem_u32(&Bs[0][bk][bn + i * 4]), bsrc + i * 4);
    CP_COMMIT();
    As[0][akg + 0][am] = ra0.x;
    As[0][akg + 1][am] = ra0.y;
    As[0][akg + 2][am] = ra0.z;
    As[0][akg + 3][am] = ra0.w;
    As[0][akg + 4][am] = ra1.x;
    As[0][akg + 5][am] = ra1.y;
    As[0][akg + 6][am] = ra1.z;
    As[0][akg + 7][am] = ra1.w;
    CP_WAIT0();
  }
  __syncthreads();

#pragma unroll 1
  for (int c = 0; c < CHKS; c++) {
    const int cur = c & 1;
    const int nxtb = cur ^ 1;
    float4 ra0, ra1;
    const bool more = (c + 1 < CHKS);
    if (more) {
      const int k0 = (c + 1) * KC3;
      ra0 = aval ? *(const float4*)(arow + k0) : make_float4(0.f, 0.f, 0.f, 0.f);
      ra1 = aval ? *(const float4*)(arow + k0 + 4) : make_float4(0.f, 0.f, 0.f, 0.f);
      const float* bs = bsrc + (size_t)k0 * CMID;
#pragma unroll
      for (int i = 0; i < 4; i++) cp16(smem_u32(&Bs[nxtb][bk][bn + i * 4]), bs + i * 4);
      CP_COMMIT();
    }
#pragma unroll
    for (int k = 0; k < KC3; k++) {
      float4 a0 = *(const float4*)&As[cur][k][am_off];
      float4 a1 = *(const float4*)&As[cur][k][am_off + 4];
      float4 b0 = *(const float4*)&Bs[cur][k][bn_off];
      float4 b1 = *(const float4*)&Bs[cur][k][bn_off + 4];
      float af[8] = {a0.x, a0.y, a0.z, a0.w, a1.x, a1.y, a1.z, a1.w};
      float bf[8] = {b0.x, b0.y, b0.z, b0.w, b1.x, b1.y, b1.z, b1.w};
#pragma unroll
      for (int i = 0; i < 8; i++)
#pragma unroll
        for (int j = 0; j < 8; j++) acc[i][j] = fmaf(af[i], bf[j], acc[i][j]);
    }
    if (more) {
      As[nxtb][akg + 0][am] = ra0.x;
      As[nxtb][akg + 1][am] = ra0.y;
      As[nxtb][akg + 2][am] = ra0.z;
      As[nxtb][akg + 3][am] = ra0.w;
      As[nxtb][akg + 4][am] = ra1.x;
      As[nxtb][akg + 5][am] = ra1.y;
      As[nxtb][akg + 6][am] = ra1.z;
      As[nxtb][akg + 7][am] = ra1.w;
      CP_WAIT0();
    }
    __syncthreads();
  }

  float* base = g_partial + (size_t)tz * (NPIX * CMID);
#pragma unroll
  for (int i = 0; i < 8; i++) {
    const int mr = mt * 64 + am_off + i;
    float* dst = &base[(size_t)mr * CMID + n0 + bn_off];
    *(float4*)dst = make_float4(acc[i][0], acc[i][1], acc[i][2], acc[i][3]);
    *(float4*)(dst + 4) = make_float4(acc[i][4], acc[i][5], acc[i][6], acc[i][7]);
  }
}

// ---------------- K2: reduce 18 partials + bias + relu ----------------
__global__ __launch_bounds__(256) void reduce_bias_relu(const float* __restrict__ bias) {
  int i = blockIdx.x * 256 + threadIdx.x;
  float s = bias[i & 255];
#pragma unroll
  for (int t = 0; t < NPLANE; t++) s += g_partial[(size_t)t * (NPIX * CMID) + i];
  g_x[i] = fmaxf(s, 0.f);
}

// ---------------- K3: 1x1 heads + score + anchor decode (zeroes g_rank too) ----------------
__global__ __launch_bounds__(32) void head_conv_kernel(
    const float* __restrict__ cls_w, const float* __restrict__ cls_b,
    const float* __restrict__ reg_w, const float* __restrict__ reg_b) {
  const int p = blockIdx.x;
  const int lane = threadIdx.x;
  const float* xr = g_x + (size_t)p * CMID;
  float acc[30];
#pragma unroll
  for (int o = 0; o < 30; o++) acc[o] = 0.f;
  for (int k = lane; k < CMID; k += 32) {
    float xv = xr[k];
    const float* wc = cls_w + (size_t)k * 10;
#pragma unroll
    for (int o = 0; o < 10; o++) acc[o] = fmaf(xv, wc[o], acc[o]);
    const float* wr = reg_w + (size_t)k * 20;
#pragma unroll
    for (int o = 0; o < 20; o++) acc[10 + o] = fmaf(xv, wr[o], acc[10 + o]);
  }
#pragma unroll
  for (int o = 0; o < 30; o++) {
#pragma unroll
    for (int s = 16; s > 0; s >>= 1) acc[o] += __shfl_xor_sync(0xffffffffu, acc[o], s);
  }
  if (lane < NA) {
    const int a = lane;
    float l0 = acc[2 * a + 0] + cls_b[2 * a + 0];
    float l1 = acc[2 * a + 1] + cls_b[2 * a + 1];
    float score = 1.f / (1.f + expf(l0 - l1));
    float d0 = acc[10 + 4 * a + 0] + reg_b[4 * a + 0];
    float d1 = acc[10 + 4 * a + 1] + reg_b[4 * a + 1];
    float d2 = acc[10 + 4 * a + 2] + reg_b[4 * a + 2];
    float d3 = acc[10 + 4 * a + 3] + reg_b[4 * a + 3];
    float base = 32.f * (float)(1 << a);
    float wdt = expf(d2) * base;
    float hgt = expf(d3) * base;
    float xc = (float)(p % WW) + d0;
    float yc = (float)(p / WW) + d1;
    const int n = p * NA + a;
    g_scores[n] = score;
    float4 b = make_float4(xc - 0.5f * wdt, yc - 0.5f * hgt,
                           xc + 0.5f * wdt, yc + 0.5f * hgt);
    *(float4*)&g_boxes[n * 4] = b;
  }
  // zero ranks (5 per pixel block)
  if (lane < NA) g_rank[p * NA + lane] = 0;
}

// ---------------- K4a: counting rank (stable sort replacement) ----------------
// grid (125 i-blocks, 8 j-chunks), 64 threads. rank[i] = #{key_j < key_i}.
__global__ __launch_bounds__(64) void rank_kernel() {
  __shared__ unsigned long long skey[1000];
  const int i = blockIdx.x * 64 + threadIdx.x;
  const int j0 = blockIdx.y * 1000;
  const unsigned long long mykey = score_key(i);
  for (int jj = threadIdx.x; jj < 1000; jj += 64) skey[jj] = score_key(j0 + jj);
  __syncthreads();
  int cnt = 0;
#pragma unroll 4
  for (int jj = 0; jj < 1000; jj++) cnt += (int)(skey[jj] < mykey);
  if (cnt) atomicAdd(&g_rank[i], cnt);
}

// ---------------- K4b: scatter boxes into sorted order ----------------
__global__ __launch_bounds__(256) void scatter_kernel() {
  const int i = blockIdx.x * 256 + threadIdx.x;
  if (i < NBOX) {
    const int r = g_rank[i];
    *(float4*)&g_boxsorted[r * 4] = *(const float4*)&g_boxes[i * 4];
  }
}

// ---------------- K4c: IoU suppression masks, 64x64 tiles ----------------
// grid (125 colblk, 125 rowblk), 64 threads. mask[i][cb] bit jj set iff
// j = cb*64+jj > i and IoU(i,j) >= 0.7.
__global__ __launch_bounds__(64) void mask_kernel() {
  const int cb = blockIdx.x, rb = blockIdx.y;
  const int tid = threadIdx.x;
  const int i = rb * 64 + tid;
  if (cb < rb) {  // strictly lower triangle: all-zero words
    g_mask[(size_t)i * NWORD + cb] = 0ull;
    return;
  }
  __shared__ float cx1[64], cy1[64], cx2[64], cy2[64], car[64];
  {
    const int j = cb * 64 + tid;
    float4 b = *(const float4*)&g_boxsorted[j * 4];
    cx1[tid] = b.x; cy1[tid] = b.y; cx2[tid] = b.z; cy2[tid] = b.w;
    car[tid] = (b.z - b.x) * (b.w - b.y);
  }
  __syncthreads();
  float4 bi = *(const float4*)&g_boxsorted[i * 4];
  const float ia = (bi.z - bi.x) * (bi.w - bi.y);
  unsigned long long w = 0ull;
#pragma unroll 4
  for (int jj = 0; jj < 64; jj++) {
    const int j = cb * 64 + jj;
    float iw = fmaxf(fminf(bi.z, cx2[jj]) - fmaxf(bi.x, cx1[jj]), 0.f);
    float ih = fmaxf(fminf(bi.w, cy2[jj]) - fmaxf(bi.y, cy1[jj]), 0.f);
    float inter = iw * ih;
    float iou = inter / (ia + car[jj] - inter);
    if (j > i && iou >= 0.7f) w |= (1ull << jj);
  }
  g_mask[(size_t)i * NWORD + cb] = w;
}

// ---------------- K5: single-warp greedy scan over precomputed masks ----------------
__global__ __launch_bounds__(32) void nms_scan_kernel() {
  __shared__ unsigned long long remv[NWORD];
  __shared__ int ssel[MAXDET];
  __shared__ int s_i;
  const int lane = threadIdx.x;
  for (int w = lane; w < NWORD; w += 32) remv[w] = 0ull;
  __syncwarp();

  int count = 0, cur = 0;
  while (count < MAXDET) {
    if (lane == 0) {
      int found = -1;
      int w = cur >> 6;
      while (w < NWORD) {
        unsigned long long mw = ~remv[w];
        if (w == (cur >> 6)) mw &= (~0ull) << (cur & 63);
        if (mw) { found = (w << 6) + (__ffsll((long long)mw) - 1); break; }
        w++;
      }
      s_i = found;
    }
    __syncwarp();
    const int i = s_i;
    if (i < 0) break;
    if (lane == 0) ssel[count] = i;
    count++;
    cur = i + 1;
    const unsigned long long* row = g_mask + (size_t)i * NWORD;
#pragma unroll
    for (int b = 0; b < 4; b++) {
      const int w = lane + b * 32;
      if (w < NWORD) remv[w] |= row[w];
    }
    __syncwarp();
  }
  __syncwarp();
  for (int r = lane; r < MAXDET; r += 32) {
    float4 v = make_float4(0.f, 0.f, 0.f, 0.f);
    if (r < count) v = *(const float4*)&g_boxsorted[ssel[r] * 4];
    *(float4*)&g_rois[r * 4] = v;
  }
}

// ---------------- K6: FC head on 300 ROIs + final outputs ----------------
__global__ __launch_bounds__(128) void fc_head_kernel(
    const float* __restrict__ fc1_w, const float* __restrict__ fc1_b,
    const float* __restrict__ clsh_w, const float* __restrict__ clsh_b,
    const float* __restrict__ regh_w, const float* __restrict__ regh_b,
    float* __restrict__ out) {
  const int r = blockIdx.x;
  const int t = threadIdx.x;
  float4 roi = *(const float4*)&g_rois[r * 4];
  float part[8];
#pragma unroll
  for (int o = 0; o < 8; o++) part[o] = 0.f;
  for (int j = t; j < 1024; j += 128) {
    float f = fc1_b[j] + roi.x * fc1_w[j] + roi.y * fc1_w[1024 + j] +
              roi.z * fc1_w[2048 + j] + roi.w * fc1_w[3072 + j];
    f = fmaxf(f, 0.f);
    float4 cw = *(const float4*)&clsh_w[j * 4];
    float4 rw = *(const float4*)&regh_w[j * 4];
    part[0] += f * cw.x; part[1] += f * cw.y; part[2] += f * cw.z; part[3] += f * cw.w;
    part[4] += f * rw.x; part[5] += f * rw.y; part[6] += f * rw.z; part[7] += f * rw.w;
  }
#pragma unroll
  for (int o = 0; o < 8; o++) {
#pragma unroll
    for (int s = 16; s > 0; s >>= 1) part[o] += __shfl_xor_sync(0xffffffffu, part[o], s);
  }
  __shared__ float wred[4][8];
  const int warp = t >> 5, lane = t & 31;
  if (lane == 0) {
#pragma unroll
    for (int o = 0; o < 8; o++) wred[warp][o] = part[o];
  }
  __syncthreads();
  if (t == 0) {
    float v[8];
#pragma unroll
    for (int o = 0; o < 8; o++) v[o] = wred[0][o] + wred[1][o] + wred[2][o] + wred[3][o];
    float l0 = v[0] + clsh_b[0], l1 = v[1] + clsh_b[1];
    float l2 = v[2] + clsh_b[2], l3 = v[3] + clsh_b[3];
    float mx = fmaxf(fmaxf(l0, l1), fmaxf(l2, l3));
    float e0 = expf(l0 - mx), e1 = expf(l1 - mx), e2 = expf(l2 - mx), e3 = expf(l3 - mx);
    float inv = 1.f / (e0 + e1 + e2 + e3);
    out[r * 4 + 0] = e0 * inv;
    out[r * 4 + 1] = e1 * inv;
    out[r * 4 + 2] = e2 * inv;
    out[r * 4 + 3] = e3 * inv;
    out[1200 + r * 4 + 0] = v[4] + regh_b[0];
    out[1200 + r * 4 + 1] = v[5] + regh_b[1];
    out[1200 + r * 4 + 2] = v[6] + regh_b[2];
    out[1200 + r * 4 + 3] = v[7] + regh_b[3];
    *(float4*)&out[2400 + r * 4] = roi;
  }
}

// ---------------- launch ----------------
extern "C" void kernel_launch(void* const* d_in, const int* in_sizes, int n_in,
                              void* d_out, int out_size) {
  const float* feat   = (const float*)d_in[0];
  const float* conv_w = (const float*)d_in[1];
  const float* conv_b = (const float*)d_in[2];
  const float* cls_w  = (const float*)d_in[3];
  const float* cls_b  = (const float*)d_in[4];
  const float* reg_w  = (const float*)d_in[5];
  const float* reg_b  = (const float*)d_in[6];
  const float* fc1_w  = (const float*)d_in[7];
  const float* fc1_b  = (const float*)d_in[8];
  const float* clsh_w = (const float*)d_in[9];
  const float* clsh_b = (const float*)d_in[10];
  const float* regh_w = (const float*)d_in[11];
  const float* regh_b = (const float*)d_in[12];
  float* out = (float*)d_out;

  (void)in_sizes; (void)n_in; (void)out_size;

  conv_ffma_kernel<<<dim3(25, 2, NPLANE), 128>>>(feat, conv_w);
  reduce_bias_relu<<<1600, 256>>>(conv_b);
  head_conv_kernel<<<1600, 32>>>(cls_w, cls_b, reg_w, reg_b);
  rank_kernel<<<dim3(125, 8), 64>>>();
  scatter_kernel<<<(NBOX + 255) / 256, 256>>>();
  mask_kernel<<<dim3(NWORD, NWORD), 64>>>();
  nms_scan_kernel<<<1, 32>>>();
  fc_head_kernel<<<300, 128>>>(fc1_w, fc1_b, clsh_w, clsh_b, regh_w, regh_b, out);
}

// round 9
// speedup vs baseline: 2.5311x; 1.4931x over previous
#include <cuda_runtime.h>
#include <math.h>
#include <stdint.h>

#define HH 40
#define WW 40
#define CIN 2048
#define NPIX 1600
#define CMID 256
#define NA 5
#define NBOX 8000
#define NWORD 125
#define MAXDET 300

#define NTILE 400            // 20x20 winograd output tiles
#define NTILEP 448           // padded to 7*64
#define VSTRIDE (NTILE * CIN)
#define KSTRIDE (CIN * CMID)
#define DSTRIDE (NTILEP * CMID)
#define KC3 16
#define KPS 512              // k per GEMM slice
#define CHKS (KPS / KC3)     // 32 chunks

// ---------------- device scratch (static, no allocation) ----------------
__device__ float g_Vt[16 * VSTRIDE];        // transformed input  [xi][tile][k]
__device__ float g_Wt[16 * KSTRIDE];        // transformed weights [xi][k][n]
__device__ float g_D[64 * DSTRIDE];         // GEMM out [xi*4+ks][tile][n]
__device__ float g_x[NPIX * CMID];
__device__ float g_scores[NBOX];
__device__ float g_boxes[NBOX * 4];
__device__ float g_boxsorted[NBOX * 4];
__device__ int g_rank[NBOX];
__device__ unsigned long long g_mask[(size_t)NBOX * NWORD];
__device__ float g_rois[MAXDET * 4];

__device__ __forceinline__ uint32_t smem_u32(const void* p) {
  uint32_t a;
  asm("{ .reg .u64 t; cvta.to.shared.u64 t, %1; cvt.u32.u64 %0, t; }" : "=r"(a) : "l"(p));
  return a;
}
__device__ __forceinline__ void cp16(uint32_t dst, const void* src) {
  asm volatile("cp.async.ca.shared.global [%0], [%1], 16;" ::"r"(dst), "l"(src) : "memory");
}
#define CP_COMMIT() asm volatile("cp.async.commit_group;" ::: "memory")
#define CP_WAIT0() asm volatile("cp.async.wait_group 0;" ::: "memory")

__device__ __forceinline__ unsigned long long score_key(int i) {
  uint32_t u = __float_as_uint(g_scores[i]);
  uint32_t ou = (u & 0x80000000u) ? ~u : (u | 0x80000000u);
  return ((unsigned long long)(~ou) << 13) | (unsigned)i;
}

// ---------------- K0a: weight transform  U = G g G^T ----------------
__global__ __launch_bounds__(256) void wt_kernel(const float* __restrict__ w) {
  const int idx = blockIdx.x * 256 + threadIdx.x;  // 524288
  const int k = idx >> 8, n = idx & 255;
  float g[3][3];
#pragma unroll
  for (int i = 0; i < 3; i++)
#pragma unroll
    for (int j = 0; j < 3; j++) g[i][j] = w[(size_t)(i * 3 + j) * KSTRIDE + idx];
  float T[4][3];
#pragma unroll
  for (int j = 0; j < 3; j++) {
    T[0][j] = g[0][j];
    T[1][j] = 0.5f * (g[0][j] + g[1][j] + g[2][j]);
    T[2][j] = 0.5f * (g[0][j] - g[1][j] + g[2][j]);
    T[3][j] = g[2][j];
  }
#pragma unroll
  for (int i = 0; i < 4; i++) {
    float u0 = T[i][0];
    float u1 = 0.5f * (T[i][0] + T[i][1] + T[i][2]);
    float u2 = 0.5f * (T[i][0] - T[i][1] + T[i][2]);
    float u3 = T[i][2];
    g_Wt[(size_t)(i * 4 + 0) * KSTRIDE + idx] = u0;
    g_Wt[(size_t)(i * 4 + 1) * KSTRIDE + idx] = u1;
    g_Wt[(size_t)(i * 4 + 2) * KSTRIDE + idx] = u2;
    g_Wt[(size_t)(i * 4 + 3) * KSTRIDE + idx] = u3;
  }
  (void)k; (void)n;
}

// ---------------- K0b: input transform  V = B^T d B ----------------
__global__ __launch_bounds__(256) void vt_kernel(const float* __restrict__ feat) {
  const int idx = blockIdx.x * 256 + threadIdx.x;  // 819200
  const int tile = idx >> 11, k = idx & 2047;
  const int ty = tile / 20, tx = tile % 20;
  const int oy = 2 * ty - 1, ox = 2 * tx - 1;
  float d[4][4];
#pragma unroll
  for (int i = 0; i < 4; i++) {
    const int py = oy + i;
    const bool yok = (py >= 0 && py < HH);
#pragma unroll
    for (int j = 0; j < 4; j++) {
      const int px = ox + j;
      d[i][j] = (yok && px >= 0 && px < WW)
                    ? feat[(size_t)(py * WW + px) * CIN + k] : 0.f;
    }
  }
  float T[4][4];
#pragma unroll
  for (int j = 0; j < 4; j++) {
    T[0][j] = d[0][j] - d[2][j];
    T[1][j] = d[1][j] + d[2][j];
    T[2][j] = d[2][j] - d[1][j];
    T[3][j] = d[1][j] - d[3][j];
  }
  const size_t base = (size_t)tile * CIN + k;
#pragma unroll
  for (int i = 0; i < 4; i++) {
    float v0 = T[i][0] - T[i][2];
    float v1 = T[i][1] + T[i][2];
    float v2 = T[i][2] - T[i][1];
    float v3 = T[i][1] - T[i][3];
    g_Vt[(size_t)(i * 4 + 0) * VSTRIDE + base] = v0;
    g_Vt[(size_t)(i * 4 + 1) * VSTRIDE + base] = v1;
    g_Vt[(size_t)(i * 4 + 2) * VSTRIDE + base] = v2;
    g_Vt[(size_t)(i * 4 + 3) * VSTRIDE + base] = v3;
  }
}

// ---------------- K1: winograd GEMM, 64x128 tile, 8x8/thread ----------------
// grid (7 m-tiles, 2 n-tiles, 64 = xi*4+ks) = 896 blocks.
__global__ __launch_bounds__(128) void wino_gemm_kernel() {
  __shared__ __align__(16) float As[2][KC3][64];
  __shared__ __align__(16) float Bs[2][KC3][128];

  const int mt = blockIdx.x;
  const int nt = blockIdx.y;
  const int z = blockIdx.z;
  const int xi = z >> 2;
  const int ks = z & 3;
  const int tid = threadIdx.x;
  const int warp = tid >> 5;
  const int lane = tid & 31;
  const int rg = lane >> 2;
  const int cg = lane & 3;
  const int am_off = rg * 8;
  const int bn_off = warp * 32 + cg * 8;

  const int am = tid & 63;
  const int akg = (tid >> 6) * 8;
  const int m = mt * 64 + am;
  const bool aval = (m < NTILE);
  const float* arow =
      g_Vt + (size_t)xi * VSTRIDE + (size_t)(aval ? m : 0) * CIN + ks * KPS + akg;

  const int bk = tid >> 3;
  const int bn = (tid & 7) * 16;
  const int n0 = nt * 128;
  const float* bsrc = g_Wt + (size_t)xi * KSTRIDE + (size_t)(ks * KPS + bk) * CMID + n0 + bn;

  float acc[8][8];
#pragma unroll
  for (int i = 0; i < 8; i++)
#pragma unroll
    for (int j = 0; j < 8; j++) acc[i][j] = 0.f;

  {
    float4 ra0 = aval ? *(const float4*)arow : make_float4(0.f, 0.f, 0.f, 0.f);
    float4 ra1 = aval ? *(const float4*)(arow + 4) : make_float4(0.f, 0.f, 0.f, 0.f);
#pragma unroll
    for (int i = 0; i < 4; i++) cp16(smem_u32(&Bs[0][bk][bn + i * 4]), bsrc + i * 4);
    CP_COMMIT();
    As[0][akg + 0][am] = ra0.x;
    As[0][akg + 1][am] = ra0.y;
    As[0][akg + 2][am] = ra0.z;
    As[0][akg + 3][am] = ra0.w;
    As[0][akg + 4][am] = ra1.x;
    As[0][akg + 5][am] = ra1.y;
    As[0][akg + 6][am] = ra1.z;
    As[0][akg + 7][am] = ra1.w;
    CP_WAIT0();
  }
  __syncthreads();

#pragma unroll 1
  for (int c = 0; c < CHKS; c++) {
    const int cur = c & 1;
    const int nxtb = cur ^ 1;
    float4 ra0, ra1;
    const bool more = (c + 1 < CHKS);
    if (more) {
      const int k0 = (c + 1) * KC3;
      ra0 = aval ? *(const float4*)(arow + k0) : make_float4(0.f, 0.f, 0.f, 0.f);
      ra1 = aval ? *(const float4*)(arow + k0 + 4) : make_float4(0.f, 0.f, 0.f, 0.f);
      const float* bs = bsrc + (size_t)k0 * CMID;
#pragma unroll
      for (int i = 0; i < 4; i++) cp16(smem_u32(&Bs[nxtb][bk][bn + i * 4]), bs + i * 4);
      CP_COMMIT();
    }
#pragma unroll
    for (int k = 0; k < KC3; k++) {
      float4 a0 = *(const float4*)&As[cur][k][am_off];
      float4 a1 = *(const float4*)&As[cur][k][am_off + 4];
      float4 b0 = *(const float4*)&Bs[cur][k][bn_off];
      float4 b1 = *(const float4*)&Bs[cur][k][bn_off + 4];
      float af[8] = {a0.x, a0.y, a0.z, a0.w, a1.x, a1.y, a1.z, a1.w};
      float bf[8] = {b0.x, b0.y, b0.z, b0.w, b1.x, b1.y, b1.z, b1.w};
#pragma unroll
      for (int i = 0; i < 8; i++)
#pragma unroll
        for (int j = 0; j < 8; j++) acc[i][j] = fmaf(af[i], bf[j], acc[i][j]);
    }
    if (more) {
      As[nxtb][akg + 0][am] = ra0.x;
      As[nxtb][akg + 1][am] = ra0.y;
      As[nxtb][akg + 2][am] = ra0.z;
      As[nxtb][akg + 3][am] = ra0.w;
      As[nxtb][akg + 4][am] = ra1.x;
      As[nxtb][akg + 5][am] = ra1.y;
      As[nxtb][akg + 6][am] = ra1.z;
      As[nxtb][akg + 7][am] = ra1.w;
      CP_WAIT0();
    }
    __syncthreads();
  }

  float* base = g_D + (size_t)z * DSTRIDE;
#pragma unroll
  for (int i = 0; i < 8; i++) {
    const int mr = mt * 64 + am_off + i;  // < 448, padded plane
    float* dst = &base[(size_t)mr * CMID + n0 + bn_off];
    *(float4*)dst = make_float4(acc[i][0], acc[i][1], acc[i][2], acc[i][3]);
    *(float4*)(dst + 4) = make_float4(acc[i][4], acc[i][5], acc[i][6], acc[i][7]);
  }
}

// ---------------- K2: inverse transform + bias + relu ----------------
// block = one tile (256 threads = n), Y = A^T M A
__global__ __launch_bounds__(256) void inv_kernel(const float* __restrict__ bias) {
  const int tile = blockIdx.x;
  const int n = threadIdx.x;
  const int ty = tile / 20, tx = tile % 20;
  const size_t off = (size_t)tile * CMID + n;
  float M[4][4];
#pragma unroll
  for (int i = 0; i < 4; i++)
#pragma unroll
    for (int j = 0; j < 4; j++) {
      const int xi = i * 4 + j;
      float s = g_D[(size_t)(xi * 4 + 0) * DSTRIDE + off] +
                g_D[(size_t)(xi * 4 + 1) * DSTRIDE + off] +
                g_D[(size_t)(xi * 4 + 2) * DSTRIDE + off] +
                g_D[(size_t)(xi * 4 + 3) * DSTRIDE + off];
      M[i][j] = s;
    }
  float S[2][4];
#pragma unroll
  for (int j = 0; j < 4; j++) {
    S[0][j] = M[0][j] + M[1][j] + M[2][j];
    S[1][j] = M[1][j] - M[2][j] - M[3][j];
  }
  const float b = bias[n];
#pragma unroll
  for (int a = 0; a < 2; a++) {
    float y0 = S[a][0] + S[a][1] + S[a][2] + b;
    float y1 = S[a][1] - S[a][2] - S[a][3] + b;
    const int py = 2 * ty + a;
    g_x[(size_t)(py * WW + 2 * tx) * CMID + n] = fmaxf(y0, 0.f);
    g_x[(size_t)(py * WW + 2 * tx + 1) * CMID + n] = fmaxf(y1, 0.f);
  }
}

// ---------------- K3: 1x1 heads + score + anchor decode ----------------
__global__ __launch_bounds__(32) void head_conv_kernel(
    const float* __restrict__ cls_w, const float* __restrict__ cls_b,
    const float* __restrict__ reg_w, const float* __restrict__ reg_b) {
  const int p = blockIdx.x;
  const int lane = threadIdx.x;
  const float* xr = g_x + (size_t)p * CMID;
  float acc[30];
#pragma unroll
  for (int o = 0; o < 30; o++) acc[o] = 0.f;
  for (int k = lane; k < CMID; k += 32) {
    float xv = xr[k];
    const float* wc = cls_w + (size_t)k * 10;
#pragma unroll
    for (int o = 0; o < 10; o++) acc[o] = fmaf(xv, wc[o], acc[o]);
    const float* wr = reg_w + (size_t)k * 20;
#pragma unroll
    for (int o = 0; o < 20; o++) acc[10 + o] = fmaf(xv, wr[o], acc[10 + o]);
  }
#pragma unroll
  for (int o = 0; o < 30; o++) {
#pragma unroll
    for (int s = 16; s > 0; s >>= 1) acc[o] += __shfl_xor_sync(0xffffffffu, acc[o], s);
  }
  if (lane < NA) {
    const int a = lane;
    float l0 = acc[2 * a + 0] + cls_b[2 * a + 0];
    float l1 = acc[2 * a + 1] + cls_b[2 * a + 1];
    float score = 1.f / (1.f + expf(l0 - l1));
    float d0 = acc[10 + 4 * a + 0] + reg_b[4 * a + 0];
    float d1 = acc[10 + 4 * a + 1] + reg_b[4 * a + 1];
    float d2 = acc[10 + 4 * a + 2] + reg_b[4 * a + 2];
    float d3 = acc[10 + 4 * a + 3] + reg_b[4 * a + 3];
    float base = 32.f * (float)(1 << a);
    float wdt = expf(d2) * base;
    float hgt = expf(d3) * base;
    float xc = (float)(p % WW) + d0;
    float yc = (float)(p / WW) + d1;
    const int n = p * NA + a;
    g_scores[n] = score;
    float4 b = make_float4(xc - 0.5f * wdt, yc - 0.5f * hgt,
                           xc + 0.5f * wdt, yc + 0.5f * hgt);
    *(float4*)&g_boxes[n * 4] = b;
  }
  if (lane < NA) g_rank[p * NA + lane] = 0;
}

// ---------------- K4a: counting rank ----------------
__global__ __launch_bounds__(64) void rank_kernel() {
  __shared__ unsigned long long skey[1000];
  const int i = blockIdx.x * 64 + threadIdx.x;
  const int j0 = blockIdx.y * 1000;
  const unsigned long long mykey = score_key(i);
  for (int jj = threadIdx.x; jj < 1000; jj += 64) skey[jj] = score_key(j0 + jj);
  __syncthreads();
  int cnt = 0;
#pragma unroll 4
  for (int jj = 0; jj < 1000; jj++) cnt += (int)(skey[jj] < mykey);
  if (cnt) atomicAdd(&g_rank[i], cnt);
}

// ---------------- K4b: scatter ----------------
__global__ __launch_bounds__(256) void scatter_kernel() {
  const int i = blockIdx.x * 256 + threadIdx.x;
  if (i < NBOX) {
    const int r = g_rank[i];
    *(float4*)&g_boxsorted[r * 4] = *(const float4*)&g_boxes[i * 4];
  }
}

// ---------------- K4c: IoU masks ----------------
__global__ __launch_bounds__(64) void mask_kernel() {
  const int cb = blockIdx.x, rb = blockIdx.y;
  const int tid = threadIdx.x;
  const int i = rb * 64 + tid;
  if (cb < rb) {
    g_mask[(size_t)i * NWORD + cb] = 0ull;
    return;
  }
  __shared__ float cx1[64], cy1[64], cx2[64], cy2[64], car[64];
  {
    const int j = cb * 64 + tid;
    float4 b = *(const float4*)&g_boxsorted[j * 4];
    cx1[tid] = b.x; cy1[tid] = b.y; cx2[tid] = b.z; cy2[tid] = b.w;
    car[tid] = (b.z - b.x) * (b.w - b.y);
  }
  __syncthreads();
  float4 bi = *(const float4*)&g_boxsorted[i * 4];
  const float ia = (bi.z - bi.x) * (bi.w - bi.y);
  unsigned long long w = 0ull;
#pragma unroll 4
  for (int jj = 0; jj < 64; jj++) {
    const int j = cb * 64 + jj;
    float iw = fmaxf(fminf(bi.z, cx2[jj]) - fmaxf(bi.x, cx1[jj]), 0.f);
    float ih = fmaxf(fminf(bi.w, cy2[jj]) - fmaxf(bi.y, cy1[jj]), 0.f);
    float inter = iw * ih;
    float iou = inter / (ia + car[jj] - inter);
    if (j > i && iou >= 0.7f) w |= (1ull << jj);
  }
  g_mask[(size_t)i * NWORD + cb] = w;
}

// ---------------- K5: single-warp greedy scan ----------------
__global__ __launch_bounds__(32) void nms_scan_kernel() {
  __shared__ unsigned long long remv[NWORD];
  __shared__ int ssel[MAXDET];
  __shared__ int s_i;
  const int lane = threadIdx.x;
  for (int w = lane; w < NWORD; w += 32) remv[w] = 0ull;
  __syncwarp();

  int count = 0, cur = 0;
  while (count < MAXDET) {
    if (lane == 0) {
      int found = -1;
      int w = cur >> 6;
      while (w < NWORD) {
        unsigned long long mw = ~remv[w];
        if (w == (cur >> 6)) mw &= (~0ull) << (cur & 63);
        if (mw) { found = (w << 6) + (__ffsll((long long)mw) - 1); break; }
        w++;
      }
      s_i = found;
    }
    __syncwarp();
    const int i = s_i;
    if (i < 0) break;
    if (lane == 0) ssel[count] = i;
    count++;
    cur = i + 1;
    const unsigned long long* row = g_mask + (size_t)i * NWORD;
#pragma unroll
    for (int b = 0; b < 4; b++) {
      const int w = lane + b * 32;
      if (w < NWORD) remv[w] |= row[w];
    }
    __syncwarp();
  }
  __syncwarp();
  for (int r = lane; r < MAXDET; r += 32) {
    float4 v = make_float4(0.f, 0.f, 0.f, 0.f);
    if (r < count) v = *(const float4*)&g_boxsorted[ssel[r] * 4];
    *(float4*)&g_rois[r * 4] = v;
  }
}

// ---------------- K6: FC head on 300 ROIs + final outputs ----------------
__global__ __launch_bounds__(128) void fc_head_kernel(
    const float* __restrict__ fc1_w, const float* __restrict__ fc1_b,
    const float* __restrict__ clsh_w, const float* __restrict__ clsh_b,
    const float* __restrict__ regh_w, const float* __restrict__ regh_b,
    float* __restrict__ out) {
  const int r = blockIdx.x;
  const int t = threadIdx.x;
  float4 roi = *(const float4*)&g_rois[r * 4];
  float part[8];
#pragma unroll
  for (int o = 0; o < 8; o++) part[o] = 0.f;
  for (int j = t; j < 1024; j += 128) {
    float f = fc1_b[j] + roi.x * fc1_w[j] + roi.y * fc1_w[1024 + j] +
              roi.z * fc1_w[2048 + j] + roi.w * fc1_w[3072 + j];
    f = fmaxf(f, 0.f);
    float4 cw = *(const float4*)&clsh_w[j * 4];
    float4 rw = *(const float4*)&regh_w[j * 4];
    part[0] += f * cw.x; part[1] += f * cw.y; part[2] += f * cw.z; part[3] += f * cw.w;
    part[4] += f * rw.x; part[5] += f * rw.y; part[6] += f * rw.z; part[7] += f * rw.w;
  }
#pragma unroll
  for (int o = 0; o < 8; o++) {
#pragma unroll
    for (int s = 16; s > 0; s >>= 1) part[o] += __shfl_xor_sync(0xffffffffu, part[o], s);
  }
  __shared__ float wred[4][8];
  const int warp = t >> 5, lane = t & 31;
  if (lane == 0) {
#pragma unroll
    for (int o = 0; o < 8; o++) wred[warp][o] = part[o];
  }
  __syncthreads();
  if (t == 0) {
    float v[8];
#pragma unroll
    for (int o = 0; o < 8; o++) v[o] = wred[0][o] + wred[1][o] + wred[2][o] + wred[3][o];
    float l0 = v[0] + clsh_b[0], l1 = v[1] + clsh_b[1];
    float l2 = v[2] + clsh_b[2], l3 = v[3] + clsh_b[3];
    float mx = fmaxf(fmaxf(l0, l1), fmaxf(l2, l3));
    float e0 = expf(l0 - mx), e1 = expf(l1 - mx), e2 = expf(l2 - mx), e3 = expf(l3 - mx);
    float inv = 1.f / (e0 + e1 + e2 + e3);
    out[r * 4 + 0] = e0 * inv;
    out[r * 4 + 1] = e1 * inv;
    out[r * 4 + 2] = e2 * inv;
    out[r * 4 + 3] = e3 * inv;
    out[1200 + r * 4 + 0] = v[4] + regh_b[0];
    out[1200 + r * 4 + 1] = v[5] + regh_b[1];
    out[1200 + r * 4 + 2] = v[6] + regh_b[2];
    out[1200 + r * 4 + 3] = v[7] + regh_b[3];
    *(float4*)&out[2400 + r * 4] = roi;
  }
}

// ---------------- launch ----------------
extern "C" void kernel_launch(void* const* d_in, const int* in_sizes, int n_in,
                              void* d_out, int out_size) {
  const float* feat   = (const float*)d_in[0];
  const float* conv_w = (const float*)d_in[1];
  const float* conv_b = (const float*)d_in[2];
  const float* cls_w  = (const float*)d_in[3];
  const float* cls_b  = (const float*)d_in[4];
  const float* reg_w  = (const float*)d_in[5];
  const float* reg_b  = (const float*)d_in[6];
  const float* fc1_w  = (const float*)d_in[7];
  const float* fc1_b  = (const float*)d_in[8];
  const float* clsh_w = (const float*)d_in[9];
  const float* clsh_b = (const float*)d_in[10];
  const float* regh_w = (const float*)d_in[11];
  const float* regh_b = (const float*)d_in[12];
  float* out = (float*)d_out;

  (void)in_sizes; (void)n_in; (void)out_size;

  wt_kernel<<<(CIN * CMID) / 256, 256>>>(conv_w);
  vt_kernel<<<(NTILE * CIN) / 256, 256>>>(feat);
  wino_gemm_kernel<<<dim3(7, 2, 64), 128>>>();
  inv_kernel<<<NTILE, 256>>>(conv_b);
  head_conv_kernel<<<1600, 32>>>(cls_w, cls_b, reg_w, reg_b);
  rank_kernel<<<dim3(125, 8), 64>>>();
  scatter_kernel<<<(NBOX + 255) / 256, 256>>>();
  mask_kernel<<<dim3(NWORD, NWORD), 64>>>();
  nms_scan_kernel<<<1, 32>>>();
  fc_head_kernel<<<300, 128>>>(fc1_w, fc1_b, clsh_w, clsh_b, regh_w, regh_b, out);
}